// round 6
// baseline (speedup 1.0000x reference)
#include <cuda_runtime.h>
#include <cstdint>

// SupConLoss fused kernel — GB300 sm_103a
// labels (dtype-detect) / prep (normalize->tf32) -> symmetric fused GEMM+rowreduce
// -> finalize. Logits (8192x8192) never hit HBM; only upper-triangular tiles
// computed (C = C^T); each off-diagonal tile feeds both row- and col-side sums.

#define NR 8192
#define DD 256
#define TEMP_INV 14.2857142857142857f   // 1/0.07
#define KC 16          // K-chunk
#define NCH (DD / KC)  // 16 chunks
#define LDSA 20        // smem row stride (floats), conflict-free padding
#define NT 64          // 64x64 tile grid of 128x128 tiles
#define NTRI (NT * (NT + 1) / 2)   // 2080 upper-triangular tiles

__device__ float g_fnorm[NR * DD];   // tf32-rounded normalized features
__device__ int   g_lab[NR];
__device__ float g_sumExp[NR];
__device__ float g_sumPos[NR];
__device__ float g_cnt[NR];

// ---------------------------------------------------------------------------
// labels: detect int32 vs int64 layout, cast to g_lab.
// int64 (LE): odd u32 words are high halves of values < 512 -> all zero.
// int32: odd words nonzero with prob 1 - (1/512)^4096.
// ---------------------------------------------------------------------------
__global__ void label_kernel(const uint32_t* __restrict__ lab) {
    __shared__ int is32;
    if (threadIdx.x == 0) is32 = 0;
    __syncthreads();
    int nz = 0;
    for (int j = 1 + 2 * threadIdx.x; j < NR; j += 2 * blockDim.x)
        nz |= (__ldg(&lab[j]) != 0u);
    if (nz) is32 = 1;   // benign race, all writers store 1
    __syncthreads();
    if (is32) {
        for (int i = threadIdx.x; i < NR; i += blockDim.x)
            g_lab[i] = (int)__ldg(&lab[i]);
    } else {
        for (int i = threadIdx.x; i < NR; i += blockDim.x)
            g_lab[i] = (int)__ldg(&lab[2 * i]);   // low word
    }
}

// ---------------------------------------------------------------------------
// prep: L2 normalize rows, round to tf32, zero per-row accumulators
// ---------------------------------------------------------------------------
__global__ void prep_kernel(const float* __restrict__ feat) {
    int row  = blockIdx.x * 8 + (threadIdx.x >> 5);
    int lane = threadIdx.x & 31;
    const float* fr = feat + row * DD;
    float v[8];
    float ss = 0.f;
#pragma unroll
    for (int j = 0; j < 8; j++) { v[j] = fr[lane + 32 * j]; ss += v[j] * v[j]; }
#pragma unroll
    for (int o = 16; o; o >>= 1) ss += __shfl_xor_sync(0xffffffffu, ss, o);
    float inv = 1.f / fmaxf(sqrtf(ss), 1e-12f);
    float* dst = g_fnorm + row * DD;
#pragma unroll
    for (int j = 0; j < 8; j++) {
        float z = v[j] * inv;
        uint32_t u;
        asm("cvt.rna.tf32.f32 %0, %1;" : "=r"(u) : "f"(z));
        dst[lane + 32 * j] = __uint_as_float(u);
    }
    if (lane == 0) {
        g_sumExp[row] = 0.f;
        g_sumPos[row] = 0.f;
        g_cnt[row]    = 0.f;
    }
}

// ---------------------------------------------------------------------------
__device__ __forceinline__ void mma_tf32(float* d, const uint32_t* a,
                                         const uint32_t* b, const float* c) {
    asm volatile(
        "mma.sync.aligned.m16n8k8.row.col.f32.tf32.tf32.f32 "
        "{%0,%1,%2,%3}, {%4,%5,%6,%7}, {%8,%9}, {%10,%11,%12,%13};\n"
        : "=f"(d[0]), "=f"(d[1]), "=f"(d[2]), "=f"(d[3])
        : "r"(a[0]), "r"(a[1]), "r"(a[2]), "r"(a[3]),
          "r"(b[0]), "r"(b[1]),
          "f"(c[0]), "f"(c[1]), "f"(c[2]), "f"(c[3]));
}

#define CPASYNC16(dst_u32, src_ptr) \
    asm volatile("cp.async.cg.shared.global [%0], [%1], 16;\n" \
                 :: "r"(dst_u32), "l"(src_ptr))

// ---------------------------------------------------------------------------
// Symmetric fused GEMM + SupCon reductions.
// Grid: NTRI=2080 CTAs, linearized upper-triangular (it,jt), jt >= it.
// Off-diagonal tiles accumulate row-side (block i) AND col-side (block j).
// Warps: 4(M) x 2(N); warp tile 32x64. 2-stage cp.async double buffer.
// Static smem: 2*2*10240 + 512 + 6*512 = 44.5 KB (< 48 KB).
// ---------------------------------------------------------------------------
__global__ void __launch_bounds__(256, 2) supcon_gemm() {
    __shared__ float As[2][128 * LDSA];
    __shared__ float Bs[2][128 * LDSA];
    __shared__ int   labT[128];
    __shared__ float sE[128], sP[128], sC[128];      // row-side (block i)
    __shared__ float sE2[128], sP2[128], sC2[128];   // col-side (block j)

    // decode linear tile id -> (it, jt), jt >= it (row-major over upper triangle)
    int t = blockIdx.x;
    int it = 0;
    while (t >= NT - it) { t -= NT - it; it++; }
    const int jt = it + t;
    const bool diag = (it == jt);
    const int rowBase = it * 128;
    const int colBase = jt * 128;

    const int tid  = threadIdx.x;
    const int warp = tid >> 5, lane = tid & 31;
    const int wm = warp & 3, wn = warp >> 2;   // 4 x 2 warp grid
    const int g  = lane >> 2, tc = lane & 3;   // quad group / lane-in-group

    // per-thread cp.async slot (same every chunk)
    const int r0 = tid >> 2, q0 = (tid & 3) * 4;   // rows 0..63
    const int r1 = r0 + 64;                        // rows 64..127

    if (tid < 128) {
        labT[tid] = g_lab[colBase + tid];
        sE[tid] = 0.f;  sP[tid] = 0.f;  sC[tid] = 0.f;
        sE2[tid] = 0.f; sP2[tid] = 0.f; sC2[tid] = 0.f;
    }
    // ordered before use by the first in-loop __syncthreads

    int rloc[4];
#pragma unroll
    for (int i = 0; i < 4; i++) rloc[i] = wm * 32 + i * 8 + g;
    int rlab[4];
#pragma unroll
    for (int i = 0; i < 4; i++) rlab[i] = g_lab[rowBase + rloc[i]];

    float pE[4] = {0.f, 0.f, 0.f, 0.f};
    float pP[4] = {0.f, 0.f, 0.f, 0.f};
    float pC[4] = {0.f, 0.f, 0.f, 0.f};

    float acc[2][8][4];
#pragma unroll
    for (int mf = 0; mf < 2; mf++)
#pragma unroll
        for (int nf = 0; nf < 8; nf++)
#pragma unroll
            for (int q = 0; q < 4; q++) acc[mf][nf][q] = 0.f;

    // --- prologue: async-load chunk 0 into buffer 0 ---
    CPASYNC16((uint32_t)__cvta_generic_to_shared(&As[0][r0 * LDSA + q0]),
              g_fnorm + (rowBase + r0) * DD + q0);
    CPASYNC16((uint32_t)__cvta_generic_to_shared(&Bs[0][r0 * LDSA + q0]),
              g_fnorm + (colBase + r0) * DD + q0);
    CPASYNC16((uint32_t)__cvta_generic_to_shared(&As[0][r1 * LDSA + q0]),
              g_fnorm + (rowBase + r1) * DD + q0);
    CPASYNC16((uint32_t)__cvta_generic_to_shared(&Bs[0][r1 * LDSA + q0]),
              g_fnorm + (colBase + r1) * DD + q0);
    asm volatile("cp.async.commit_group;\n" ::: "memory");

#pragma unroll 1
    for (int kc = 0; kc < NCH; kc++) {
        asm volatile("cp.async.wait_group 0;\n" ::: "memory");
        __syncthreads();   // chunk kc visible; all warps done reading other buffer

        if (kc + 1 < NCH) {
            const int b    = (kc + 1) & 1;
            const int koff = (kc + 1) * KC;
            CPASYNC16((uint32_t)__cvta_generic_to_shared(&As[b][r0 * LDSA + q0]),
                      g_fnorm + (rowBase + r0) * DD + koff + q0);
            CPASYNC16((uint32_t)__cvta_generic_to_shared(&Bs[b][r0 * LDSA + q0]),
                      g_fnorm + (colBase + r0) * DD + koff + q0);
            CPASYNC16((uint32_t)__cvta_generic_to_shared(&As[b][r1 * LDSA + q0]),
                      g_fnorm + (rowBase + r1) * DD + koff + q0);
            CPASYNC16((uint32_t)__cvta_generic_to_shared(&Bs[b][r1 * LDSA + q0]),
                      g_fnorm + (colBase + r1) * DD + koff + q0);
            asm volatile("cp.async.commit_group;\n" ::: "memory");
        }

        const float* Ab = As[kc & 1];
        const float* Bb = Bs[kc & 1];
#pragma unroll
        for (int ks = 0; ks < 2; ks++) {
            const int k0 = ks * 8;
            uint32_t a[2][4], bf[8][2];
#pragma unroll
            for (int mf = 0; mf < 2; mf++) {
                const float* ap = Ab + (wm * 32 + mf * 16 + g) * LDSA + k0 + tc;
                a[mf][0] = __float_as_uint(ap[0]);
                a[mf][1] = __float_as_uint(ap[8 * LDSA]);
                a[mf][2] = __float_as_uint(ap[4]);
                a[mf][3] = __float_as_uint(ap[8 * LDSA + 4]);
            }
#pragma unroll
            for (int nf = 0; nf < 8; nf++) {
                const float* bp = Bb + (wn * 64 + nf * 8 + g) * LDSA + k0 + tc;
                bf[nf][0] = __float_as_uint(bp[0]);
                bf[nf][1] = __float_as_uint(bp[4]);
            }
#pragma unroll
            for (int mf = 0; mf < 2; mf++)
#pragma unroll
                for (int nf = 0; nf < 8; nf++)
                    mma_tf32(acc[mf][nf], a[mf], bf[nf], acc[mf][nf]);
        }
    }

    // --- epilogue: consume the 128x128 logits tile in-register ---
    // Row-side always; col-side (transpose contribution) only off-diagonal.
#pragma unroll
    for (int nf = 0; nf < 8; nf++) {
        const int ncl   = wn * 64 + nf * 8 + tc * 2;
        const int ncol  = colBase + ncl;
        const int clab0 = labT[ncl];
        const int clab1 = labT[ncl + 1];
        float cE0 = 0.f, cE1 = 0.f, cP0 = 0.f, cP1 = 0.f, cC0 = 0.f, cC1 = 0.f;
#pragma unroll
        for (int mf = 0; mf < 2; mf++) {
#pragma unroll
            for (int h = 0; h < 2; h++) {
                const int ri   = mf * 2 + h;
                const int grow = rowBase + rloc[ri];
                float l0 = acc[mf][nf][h * 2 + 0] * TEMP_INV;
                float l1 = acc[mf][nf][h * 2 + 1] * TEMP_INV;
                // self-pairs only possible on diagonal tiles
                bool self0 = diag && (grow == ncol);
                bool self1 = diag && (grow == ncol + 1);
                float e0 = self0 ? 0.f : __expf(l0);
                float e1 = self1 ? 0.f : __expf(l1);
                bool m0 = !self0 && (clab0 == rlab[ri]);
                bool m1 = !self1 && (clab1 == rlab[ri]);
                // row-side
                pE[ri] += e0 + e1;
                if (m0) { pP[ri] += l0; pC[ri] += 1.f; }
                if (m1) { pP[ri] += l1; pC[ri] += 1.f; }
                // col-side (symmetric logit & match predicate)
                cE0 += e0; cE1 += e1;
                if (m0) { cP0 += l0; cC0 += 1.f; }
                if (m1) { cP1 += l1; cC1 += 1.f; }
            }
        }
        if (!diag) {
            // reduce col partials over the quad-row axis g (lane bits 2..4)
#pragma unroll
            for (int o = 4; o <= 16; o <<= 1) {
                cE0 += __shfl_xor_sync(0xffffffffu, cE0, o);
                cE1 += __shfl_xor_sync(0xffffffffu, cE1, o);
                cP0 += __shfl_xor_sync(0xffffffffu, cP0, o);
                cP1 += __shfl_xor_sync(0xffffffffu, cP1, o);
                cC0 += __shfl_xor_sync(0xffffffffu, cC0, o);
                cC1 += __shfl_xor_sync(0xffffffffu, cC1, o);
            }
            if (lane < 4) {   // g == 0 lanes hold sums for their tc
                atomicAdd(&sE2[ncl], cE0);     atomicAdd(&sE2[ncl + 1], cE1);
                atomicAdd(&sP2[ncl], cP0);     atomicAdd(&sP2[ncl + 1], cP1);
                atomicAdd(&sC2[ncl], cC0);     atomicAdd(&sC2[ncl + 1], cC1);
            }
        }
    }

    // --- row-side: reduce per-thread partials over tc, then smem, then global ---
#pragma unroll
    for (int i = 0; i < 4; i++) {
        pE[i] += __shfl_xor_sync(0xffffffffu, pE[i], 1);
        pE[i] += __shfl_xor_sync(0xffffffffu, pE[i], 2);
        pP[i] += __shfl_xor_sync(0xffffffffu, pP[i], 1);
        pP[i] += __shfl_xor_sync(0xffffffffu, pP[i], 2);
        pC[i] += __shfl_xor_sync(0xffffffffu, pC[i], 1);
        pC[i] += __shfl_xor_sync(0xffffffffu, pC[i], 2);
        if (tc == 0) {
            atomicAdd(&sE[rloc[i]], pE[i]);
            atomicAdd(&sP[rloc[i]], pP[i]);
            atomicAdd(&sC[rloc[i]], pC[i]);
        }
    }
    __syncthreads();
    if (tid < 128) {
        atomicAdd(&g_sumExp[rowBase + tid], sE[tid]);
        atomicAdd(&g_sumPos[rowBase + tid], sP[tid]);
        atomicAdd(&g_cnt[rowBase + tid],    sC[tid]);
        if (!diag) {
            atomicAdd(&g_sumExp[colBase + tid], sE2[tid]);
            atomicAdd(&g_sumPos[colBase + tid], sP2[tid]);
            atomicAdd(&g_cnt[colBase + tid],    sC2[tid]);
        }
    }
}

// ---------------------------------------------------------------------------
// finalize: loss = -mean_i [ (P_i - C_i * log(S_i + 1e-6)) / max(C_i, 1) ]
// ---------------------------------------------------------------------------
__global__ void finalize_kernel(float* __restrict__ out) {
    __shared__ float red[256];
    int tid = threadIdx.x;
    float acc = 0.f;
    for (int i = tid; i < NR; i += 256) {
        float lse = logf(g_sumExp[i] + 1e-6f);
        float c   = g_cnt[i];
        acc += (g_sumPos[i] - c * lse) / fmaxf(c, 1.f);
    }
    red[tid] = acc;
    __syncthreads();
    for (int o = 128; o; o >>= 1) {
        if (tid < o) red[tid] += red[tid + o];
        __syncthreads();
    }
    if (tid == 0) out[0] = -red[0] / (float)NR;
}

// ---------------------------------------------------------------------------
extern "C" void kernel_launch(void* const* d_in, const int* in_sizes, int n_in,
                              void* d_out, int out_size) {
    const float*    feat = (const float*)d_in[0];
    const uint32_t* lab  = (const uint32_t*)d_in[1];
    label_kernel<<<1, 1024>>>(lab);
    prep_kernel<<<NR / 8, 256>>>(feat);
    supcon_gemm<<<NTRI, 256>>>();
    finalize_kernel<<<1, 256>>>((float*)d_out);
}

// round 10
// speedup vs baseline: 1.5701x; 1.5701x over previous
#include <cuda_runtime.h>
#include <cuda_bf16.h>
#include <cstdint>

// SupConLoss fused kernel — GB300 sm_103a
// labels (dtype-detect) / prep (normalize->bf16) -> symmetric fused bf16 GEMM
// (m16n8k16) + rowreduce -> parallel finalize. Logits never hit HBM; only
// upper-triangular tiles computed (C = C^T).

#define NR 8192
#define DD 256
#define TEMP_INV 14.2857142857142857f   // 1/0.07
#define KC 32          // K-chunk (bf16 elements)
#define NCH (DD / KC)  // 8 chunks
#define LDSW 20        // smem row stride in u32 words (80 B, conflict-free, 16B-mult)
#define NT 64          // 64x64 tile grid of 128x128 tiles
#define NTRI (NT * (NT + 1) / 2)   // 2080 upper-triangular tiles

__device__ __align__(16) __nv_bfloat16 g_fbf[NR * DD];  // normalized bf16 features
__device__ int   g_lab[NR];
__device__ float g_sumExp[NR];
__device__ float g_sumPos[NR];
__device__ float g_cnt[NR];
__device__ float g_loss;

// ---------------------------------------------------------------------------
// labels: detect int32 vs int64 layout, cast to g_lab; zero loss accumulator.
// int64 (LE): odd u32 words are high halves of values < 512 -> all zero.
// ---------------------------------------------------------------------------
__global__ void label_kernel(const uint32_t* __restrict__ lab) {
    __shared__ int is32;
    if (threadIdx.x == 0) { is32 = 0; g_loss = 0.f; }
    __syncthreads();
    int nz = 0;
    for (int j = 1 + 2 * threadIdx.x; j < NR; j += 2 * blockDim.x)
        nz |= (__ldg(&lab[j]) != 0u);
    if (nz) is32 = 1;   // benign race, all writers store 1
    __syncthreads();
    if (is32) {
        for (int i = threadIdx.x; i < NR; i += blockDim.x)
            g_lab[i] = (int)__ldg(&lab[i]);
    } else {
        for (int i = threadIdx.x; i < NR; i += blockDim.x)
            g_lab[i] = (int)__ldg(&lab[2 * i]);   // low word
    }
}

// ---------------------------------------------------------------------------
// prep: L2 normalize rows -> bf16, zero per-row accumulators.
// One warp per row; lane handles 8 contiguous elements (2x float4 in,
// 1x uint4 bf16 out, fully coalesced).
// ---------------------------------------------------------------------------
__global__ void prep_kernel(const float* __restrict__ feat) {
    int row  = blockIdx.x * 8 + (threadIdx.x >> 5);
    int lane = threadIdx.x & 31;
    const float4* fr4 = reinterpret_cast<const float4*>(feat + row * DD) + lane * 2;
    float4 u = fr4[0], w = fr4[1];
    float ss = u.x*u.x + u.y*u.y + u.z*u.z + u.w*u.w
             + w.x*w.x + w.y*w.y + w.z*w.z + w.w*w.w;
#pragma unroll
    for (int o = 16; o; o >>= 1) ss += __shfl_xor_sync(0xffffffffu, ss, o);
    float inv = 1.f / fmaxf(sqrtf(ss), 1e-12f);

    __nv_bfloat162 p0 = __floats2bfloat162_rn(u.x * inv, u.y * inv);
    __nv_bfloat162 p1 = __floats2bfloat162_rn(u.z * inv, u.w * inv);
    __nv_bfloat162 p2 = __floats2bfloat162_rn(w.x * inv, w.y * inv);
    __nv_bfloat162 p3 = __floats2bfloat162_rn(w.z * inv, w.w * inv);
    uint4 pk;
    pk.x = *reinterpret_cast<uint32_t*>(&p0);
    pk.y = *reinterpret_cast<uint32_t*>(&p1);
    pk.z = *reinterpret_cast<uint32_t*>(&p2);
    pk.w = *reinterpret_cast<uint32_t*>(&p3);
    reinterpret_cast<uint4*>(g_fbf + row * DD)[lane] = pk;

    if (lane == 0) {
        g_sumExp[row] = 0.f;
        g_sumPos[row] = 0.f;
        g_cnt[row]    = 0.f;
    }
}

// ---------------------------------------------------------------------------
__device__ __forceinline__ void mma_bf16(float* d, const uint32_t* a,
                                         const uint32_t* b, const float* c) {
    asm volatile(
        "mma.sync.aligned.m16n8k16.row.col.f32.bf16.bf16.f32 "
        "{%0,%1,%2,%3}, {%4,%5,%6,%7}, {%8,%9}, {%10,%11,%12,%13};\n"
        : "=f"(d[0]), "=f"(d[1]), "=f"(d[2]), "=f"(d[3])
        : "r"(a[0]), "r"(a[1]), "r"(a[2]), "r"(a[3]),
          "r"(b[0]), "r"(b[1]),
          "f"(c[0]), "f"(c[1]), "f"(c[2]), "f"(c[3]));
}

#define CPASYNC16(dst_u32, src_ptr) \
    asm volatile("cp.async.cg.shared.global [%0], [%1], 16;\n" \
                 :: "r"(dst_u32), "l"(src_ptr))

// ---------------------------------------------------------------------------
// Symmetric fused bf16 GEMM + SupCon reductions.
// Grid: NTRI=2080 CTAs, linearized upper-triangular (it,jt), jt >= it.
// CTA tile 128x128; warps 4(M) x 2(N), warp tile 32x64; m16n8k16 bf16.
// K=256 in 8 chunks of 32 (2 k-steps of 16 each). 2-stage cp.async.
// Smem tile row: 32 bf16 = 64 B, padded stride 80 B (20 u32): fragment LDS
// bank = (20g + tc) mod 32 all-distinct, cp.async rows are 4x16B aligned.
// Static smem: 2*2*10240 + 512 + 6*512 = 44.5 KB.
// ---------------------------------------------------------------------------
__global__ void __launch_bounds__(256, 2) supcon_gemm() {
    __shared__ uint32_t As[2][128 * LDSW];
    __shared__ uint32_t Bs[2][128 * LDSW];
    __shared__ int   labT[128];
    __shared__ float sE[128], sP[128], sC[128];      // row-side (block i)
    __shared__ float sE2[128], sP2[128], sC2[128];   // col-side (block j)

    // decode linear tile id -> (it, jt), jt >= it
    int t = blockIdx.x;
    int it = 0;
    while (t >= NT - it) { t -= NT - it; it++; }
    const int jt = it + t;
    const bool diag = (it == jt);
    const int rowBase = it * 128;
    const int colBase = jt * 128;

    const int tid  = threadIdx.x;
    const int warp = tid >> 5, lane = tid & 31;
    const int wm = warp & 3, wn = warp >> 2;   // 4 x 2 warp grid
    const int g  = lane >> 2, tc = lane & 3;   // quad group / lane-in-group

    // cp.async slots: per matrix 128 rows x 4 (16B) = 512 slots; 2 per thread
    const int r0 = tid >> 2, q0 = tid & 3;     // slot tid   : rows 0..63
    const int r1 = r0 + 64;                    // slot tid+256: rows 64..127

    if (tid < 128) {
        labT[tid] = g_lab[colBase + tid];
        sE[tid] = 0.f;  sP[tid] = 0.f;  sC[tid] = 0.f;
        sE2[tid] = 0.f; sP2[tid] = 0.f; sC2[tid] = 0.f;
    }
    // ordered before use by the first in-loop __syncthreads

    int rloc[4];
#pragma unroll
    for (int i = 0; i < 4; i++) rloc[i] = wm * 32 + i * 8 + g;
    int rlab[4];
#pragma unroll
    for (int i = 0; i < 4; i++) rlab[i] = g_lab[rowBase + rloc[i]];

    float pE[4] = {0.f, 0.f, 0.f, 0.f};
    float pP[4] = {0.f, 0.f, 0.f, 0.f};
    float pC[4] = {0.f, 0.f, 0.f, 0.f};

    float acc[2][8][4];
#pragma unroll
    for (int mf = 0; mf < 2; mf++)
#pragma unroll
        for (int nf = 0; nf < 8; nf++)
#pragma unroll
            for (int q = 0; q < 4; q++) acc[mf][nf][q] = 0.f;

    // --- prologue: async-load chunk 0 into buffer 0 ---
    CPASYNC16((uint32_t)__cvta_generic_to_shared(&As[0][r0 * LDSW + q0 * 4]),
              g_fbf + (rowBase + r0) * DD + q0 * 8);
    CPASYNC16((uint32_t)__cvta_generic_to_shared(&Bs[0][r0 * LDSW + q0 * 4]),
              g_fbf + (colBase + r0) * DD + q0 * 8);
    CPASYNC16((uint32_t)__cvta_generic_to_shared(&As[0][r1 * LDSW + q0 * 4]),
              g_fbf + (rowBase + r1) * DD + q0 * 8);
    CPASYNC16((uint32_t)__cvta_generic_to_shared(&Bs[0][r1 * LDSW + q0 * 4]),
              g_fbf + (colBase + r1) * DD + q0 * 8);
    asm volatile("cp.async.commit_group;\n" ::: "memory");

#pragma unroll 1
    for (int kc = 0; kc < NCH; kc++) {
        asm volatile("cp.async.wait_group 0;\n" ::: "memory");
        __syncthreads();   // chunk kc visible; all warps done reading other buffer

        if (kc + 1 < NCH) {
            const int b    = (kc + 1) & 1;
            const int koff = (kc + 1) * KC;
            CPASYNC16((uint32_t)__cvta_generic_to_shared(&As[b][r0 * LDSW + q0 * 4]),
                      g_fbf + (rowBase + r0) * DD + koff + q0 * 8);
            CPASYNC16((uint32_t)__cvta_generic_to_shared(&Bs[b][r0 * LDSW + q0 * 4]),
                      g_fbf + (colBase + r0) * DD + koff + q0 * 8);
            CPASYNC16((uint32_t)__cvta_generic_to_shared(&As[b][r1 * LDSW + q0 * 4]),
                      g_fbf + (rowBase + r1) * DD + koff + q0 * 8);
            CPASYNC16((uint32_t)__cvta_generic_to_shared(&Bs[b][r1 * LDSW + q0 * 4]),
                      g_fbf + (colBase + r1) * DD + koff + q0 * 8);
            asm volatile("cp.async.commit_group;\n" ::: "memory");
        }

        const uint32_t* Ab = As[kc & 1];
        const uint32_t* Bb = Bs[kc & 1];
#pragma unroll
        for (int ks = 0; ks < 2; ks++) {
            const int k0 = ks * 8;   // k-step offset in u32 words (16 bf16)
            uint32_t a[2][4], bf[8][2];
#pragma unroll
            for (int mf = 0; mf < 2; mf++) {
                const uint32_t* ap = Ab + (wm * 32 + mf * 16 + g) * LDSW + k0 + tc;
                a[mf][0] = ap[0];            // row g,   k-words tc
                a[mf][1] = ap[8 * LDSW];     // row g+8, k-words tc
                a[mf][2] = ap[4];            // row g,   k-words tc+4
                a[mf][3] = ap[8 * LDSW + 4]; // row g+8, k-words tc+4
            }
#pragma unroll
            for (int nf = 0; nf < 8; nf++) {
                const uint32_t* bp = Bb + (wn * 64 + nf * 8 + g) * LDSW + k0 + tc;
                bf[nf][0] = bp[0];
                bf[nf][1] = bp[4];
            }
#pragma unroll
            for (int mf = 0; mf < 2; mf++)
#pragma unroll
                for (int nf = 0; nf < 8; nf++)
                    mma_bf16(acc[mf][nf], a[mf], bf[nf], acc[mf][nf]);
        }
    }

    // --- epilogue: consume the 128x128 logits tile in-register ---
    // Row-side always; col-side (transpose contribution) only off-diagonal.
#pragma unroll
    for (int nf = 0; nf < 8; nf++) {
        const int ncl   = wn * 64 + nf * 8 + tc * 2;
        const int ncol  = colBase + ncl;
        const int clab0 = labT[ncl];
        const int clab1 = labT[ncl + 1];
        float cE0 = 0.f, cE1 = 0.f, cP0 = 0.f, cP1 = 0.f, cC0 = 0.f, cC1 = 0.f;
#pragma unroll
        for (int mf = 0; mf < 2; mf++) {
#pragma unroll
            for (int h = 0; h < 2; h++) {
                const int ri   = mf * 2 + h;
                const int grow = rowBase + rloc[ri];
                float l0 = acc[mf][nf][h * 2 + 0] * TEMP_INV;
                float l1 = acc[mf][nf][h * 2 + 1] * TEMP_INV;
                // self-pairs only possible on diagonal tiles
                bool self0 = diag && (grow == ncol);
                bool self1 = diag && (grow == ncol + 1);
                float e0 = self0 ? 0.f : __expf(l0);
                float e1 = self1 ? 0.f : __expf(l1);
                bool m0 = !self0 && (clab0 == rlab[ri]);
                bool m1 = !self1 && (clab1 == rlab[ri]);
                // row-side
                pE[ri] += e0 + e1;
                if (m0) { pP[ri] += l0; pC[ri] += 1.f; }
                if (m1) { pP[ri] += l1; pC[ri] += 1.f; }
                // col-side (symmetric logit & match predicate)
                cE0 += e0; cE1 += e1;
                if (m0) { cP0 += l0; cC0 += 1.f; }
                if (m1) { cP1 += l1; cC1 += 1.f; }
            }
        }
        if (!diag) {
            // reduce col partials over the quad-row axis g (lane bits 2..4)
#pragma unroll
            for (int o = 4; o <= 16; o <<= 1) {
                cE0 += __shfl_xor_sync(0xffffffffu, cE0, o);
                cE1 += __shfl_xor_sync(0xffffffffu, cE1, o);
                cP0 += __shfl_xor_sync(0xffffffffu, cP0, o);
                cP1 += __shfl_xor_sync(0xffffffffu, cP1, o);
                cC0 += __shfl_xor_sync(0xffffffffu, cC0, o);
                cC1 += __shfl_xor_sync(0xffffffffu, cC1, o);
            }
            if (lane < 4) {   // g == 0 lanes hold sums for their tc
                atomicAdd(&sE2[ncl], cE0);     atomicAdd(&sE2[ncl + 1], cE1);
                atomicAdd(&sP2[ncl], cP0);     atomicAdd(&sP2[ncl + 1], cP1);
                atomicAdd(&sC2[ncl], cC0);     atomicAdd(&sC2[ncl + 1], cC1);
            }
        }
    }

    // --- row-side: reduce per-thread partials over tc, then smem, then global ---
#pragma unroll
    for (int i = 0; i < 4; i++) {
        pE[i] += __shfl_xor_sync(0xffffffffu, pE[i], 1);
        pE[i] += __shfl_xor_sync(0xffffffffu, pE[i], 2);
        pP[i] += __shfl_xor_sync(0xffffffffu, pP[i], 1);
        pP[i] += __shfl_xor_sync(0xffffffffu, pP[i], 2);
        pC[i] += __shfl_xor_sync(0xffffffffu, pC[i], 1);
        pC[i] += __shfl_xor_sync(0xffffffffu, pC[i], 2);
        if (tc == 0) {
            atomicAdd(&sE[rloc[i]], pE[i]);
            atomicAdd(&sP[rloc[i]], pP[i]);
            atomicAdd(&sC[rloc[i]], pC[i]);
        }
    }
    __syncthreads();
    if (tid < 128) {
        atomicAdd(&g_sumExp[rowBase + tid], sE[tid]);
        atomicAdd(&g_sumPos[rowBase + tid], sP[tid]);
        atomicAdd(&g_cnt[rowBase + tid],    sC[tid]);
        if (!diag) {
            atomicAdd(&g_sumExp[colBase + tid], sE2[tid]);
            atomicAdd(&g_sumPos[colBase + tid], sP2[tid]);
            atomicAdd(&g_cnt[colBase + tid],    sC2[tid]);
        }
    }
}

// ---------------------------------------------------------------------------
// finalize stage 1: 32 blocks x 256 threads, one row each; block-reduce,
// atomicAdd into g_loss (zeroed in label_kernel).
// ---------------------------------------------------------------------------
__global__ void finalize1_kernel() {
    __shared__ float red[256];
    int i   = blockIdx.x * 256 + threadIdx.x;
    float lse = logf(g_sumExp[i] + 1e-6f);
    float c   = g_cnt[i];
    float v   = (g_sumPos[i] - c * lse) / fmaxf(c, 1.f);
    red[threadIdx.x] = v;
    __syncthreads();
    for (int o = 128; o; o >>= 1) {
        if (threadIdx.x < o) red[threadIdx.x] += red[threadIdx.x + o];
        __syncthreads();
    }
    if (threadIdx.x == 0) atomicAdd(&g_loss, red[0]);
}

// finalize stage 2: write result
__global__ void finalize2_kernel(float* __restrict__ out) {
    out[0] = -g_loss / (float)NR;
}

// ---------------------------------------------------------------------------
extern "C" void kernel_launch(void* const* d_in, const int* in_sizes, int n_in,
                              void* d_out, int out_size) {
    const float*    feat = (const float*)d_in[0];
    const uint32_t* lab  = (const uint32_t*)d_in[1];
    label_kernel<<<1, 1024>>>(lab);
    prep_kernel<<<NR / 8, 256>>>(feat);
    supcon_gemm<<<NTRI, 256>>>();
    finalize1_kernel<<<NR / 256, 256>>>();
    finalize2_kernel<<<1, 1>>>((float*)d_out);
}